// round 1
// baseline (speedup 1.0000x reference)
#include <cuda_runtime.h>

#define BATCH 8
#define NCH   6
#define HH    1024
#define WW    1024
#define TILE  32
#define HALO  2
#define HWIN  36   // TILE + 2*HALO
#define NPIX  (8.0f * 1024.0f * 1024.0f)

__device__ int g_tgt_is64;

// Zero the output and detect targets dtype (int64 vs int32).
// Targets values are in [0,5]; if stored as little-endian int64, every odd
// 32-bit word of the first 256 elements is 0. For genuine int32 data those
// words are uniform in [0,5] -> all-zero probability (1/6)^256 ~ 0.
__global__ void dcl_init_kernel(const int* __restrict__ tgt32, float* __restrict__ out) {
    if (threadIdx.x == 0 && blockIdx.x == 0) {
        int is64 = 1;
        for (int i = 0; i < 256; ++i) {
            if (tgt32[2 * i + 1] != 0) { is64 = 0; break; }
        }
        g_tgt_is64 = is64;
        *out = 0.0f;
    }
}

__global__ __launch_bounds__(256) void dcl_main_kernel(
    const float* __restrict__ pred,
    const void*  __restrict__ tgt,
    float* __restrict__ out)
{
    __shared__ float s_cls[HWIN][HWIN + 1];
    __shared__ float s_tgt[HWIN][HWIN + 1];
    __shared__ float hs1[HWIN][TILE];
    __shared__ float hs2[HWIN][TILE];
    __shared__ float ht1[HWIN][TILE];
    __shared__ float ht2[HWIN][TILE];

    const int tid = threadIdx.x;            // 0..255
    const int bx  = blockIdx.x * TILE;
    const int by  = blockIdx.y * TILE;
    const int b   = blockIdx.z;

    const float* p0 = pred + (size_t)b * NCH * HH * WW;
    const int is64 = g_tgt_is64;
    const long long* t64 = (const long long*)tgt + (size_t)b * HH * WW;
    const int*       t32 = (const int*)tgt       + (size_t)b * HH * WW;

    // ---- Load halo: argmax over channels + target cast ----
    for (int i = tid; i < HWIN * HWIN; i += 256) {
        const int r  = i / HWIN;
        const int c  = i - r * HWIN;
        const int gy = by + r - HALO;
        const int gx = bx + c - HALO;
        float cls = 0.0f, tv = 0.0f;
        if ((unsigned)gy < (unsigned)HH && (unsigned)gx < (unsigned)WW) {
            const size_t idx = (size_t)gy * WW + gx;
            float best = p0[idx];
            int   bi   = 0;
            #pragma unroll
            for (int ch = 1; ch < NCH; ++ch) {
                const float v = p0[idx + (size_t)ch * HH * WW];
                if (v > best) { best = v; bi = ch; }
            }
            cls = (float)bi;
            tv  = is64 ? (float)t64[idx] : (float)t32[idx];
        }
        s_cls[r][c] = cls;
        s_tgt[r][c] = tv;
    }
    __syncthreads();

    // ---- Horizontal 5-wide sums of (v, v^2) for both maps ----
    for (int i = tid; i < HWIN * TILE; i += 256) {
        const int r = i >> 5;          // / TILE
        const int c = i & (TILE - 1);  // % TILE
        float a1 = 0.f, a2 = 0.f, b1 = 0.f, b2 = 0.f;
        #pragma unroll
        for (int d = 0; d < 5; ++d) {
            const float v = s_cls[r][c + d];
            a1 += v; a2 = fmaf(v, v, a2);
            const float w = s_tgt[r][c + d];
            b1 += w; b2 = fmaf(w, w, b2);
        }
        hs1[r][c] = a1; hs2[r][c] = a2;
        ht1[r][c] = b1; ht2[r][c] = b2;
    }
    __syncthreads();

    // ---- Vertical 5-window, sliding over 4 rows per thread ----
    const int c  = tid & 31;
    const int ry = (tid >> 5) * 4;     // 0,4,...,28 (output-row base)
    float s1 = 0.f, s2 = 0.f, t1 = 0.f, t2 = 0.f;
    #pragma unroll
    for (int d = 0; d < 5; ++d) {
        s1 += hs1[ry + d][c]; s2 += hs2[ry + d][c];
        t1 += ht1[ry + d][c]; t2 += ht2[ry + d][c];
    }

    float acc = 0.0f;
    #pragma unroll
    for (int rr = 0; rr < 4; ++rr) {
        // unbiased var over 25 samples: (25*s2 - s1^2)/600
        const float vp = fmaxf(fmaf(25.0f, s2, -s1 * s1), 0.0f) * (1.0f / 600.0f);
        const float vt = fmaxf(fmaf(25.0f, t2, -t1 * t1), 0.0f) * (1.0f / 600.0f);
        const float dd = sqrtf(vp) - sqrtf(vt);
        acc = fmaf(dd, dd, acc);
        if (rr < 3) {
            const int ro = ry + rr, rn = ry + rr + 5;
            s1 += hs1[rn][c] - hs1[ro][c];
            s2 += hs2[rn][c] - hs2[ro][c];
            t1 += ht1[rn][c] - ht1[ro][c];
            t2 += ht2[rn][c] - ht2[ro][c];
        }
    }

    // ---- Reduce: warp shuffle -> smem -> atomicAdd ----
    acc *= (1.0f / NPIX);
    #pragma unroll
    for (int o = 16; o > 0; o >>= 1)
        acc += __shfl_down_sync(0xffffffffu, acc, o);

    __shared__ float warpsum[8];
    if ((tid & 31) == 0) warpsum[tid >> 5] = acc;
    __syncthreads();
    if (tid < 8) {
        float v = warpsum[tid];
        #pragma unroll
        for (int o = 4; o > 0; o >>= 1)
            v += __shfl_down_sync(0xffu, v, o);
        if (tid == 0) atomicAdd(out, v);
    }
}

extern "C" void kernel_launch(void* const* d_in, const int* in_sizes, int n_in,
                              void* d_out, int out_size) {
    const float* pred = (const float*)d_in[0];
    const void*  tgt  = d_in[1];
    float* out = (float*)d_out;

    dcl_init_kernel<<<1, 32>>>((const int*)tgt, out);

    dim3 grid(WW / TILE, HH / TILE, BATCH);
    dcl_main_kernel<<<grid, 256>>>(pred, tgt, out);
}